// round 14
// baseline (speedup 1.0000x reference)
#include <cuda_runtime.h>
#include <cuda_fp16.h>
#include <cstddef>

#define NB    512
#define NR    1152
#define NC    10
#define NO    16
#define CO    160          // NC * NO
#define NB2   256          // b-pairs

// flat-permuted inner layout: f = (o>>2)*40 + c*4 + (o&3)

typedef unsigned long long ull;

// ---------------- scratch ----------------------------------------------------------
__device__ __half2 g_uhat2[(size_t)NB2 * NR * CO];  // 189 MB fp16, (even,odd) packed, f-order
__device__ float2  g_S0[NB2 * CO];                  // raw sum_r u_hat (f-order)
__device__ float2  g_S1[NB2 * CO];                  // s from iter 1   (f-order)
__device__ float2  g_S2[NB2 * CO];                  // s from iter 2   (f-order)
__device__ int     g_cnt[NB2];                      // pass-2 completion counters

// ---------------- packed f32x2 helpers ---------------------------------------------
__device__ __forceinline__ ull pk2(float x, float y) {
    ull r; asm("mov.b64 %0, {%1,%2};" : "=l"(r) : "f"(x), "f"(y)); return r;
}
__device__ __forceinline__ void fma2(ull& d, ull a, ull b) {
    asm("fma.rn.f32x2 %0, %1, %2, %0;" : "+l"(d) : "l"(a), "l"(b));
}
__device__ __forceinline__ float2 upk2(ull v) {
    float2 f; asm("mov.b64 {%0,%1}, %2;" : "=f"(f.x), "=f"(f.y) : "l"(v)); return f;
}
__device__ __forceinline__ void redg_v2(float2* p, float x, float y) {
    asm volatile("red.global.add.v2.f32 [%0], {%1, %2};" :: "l"(p), "f"(x), "f"(y) : "memory");
}

// squash over a 16-lane group; all 32 lanes of the warp must call.
__device__ __forceinline__ float squash_val(float s) {
    float sq = s * s;
    sq += __shfl_xor_sync(0xffffffffu, sq, 1);
    sq += __shfl_xor_sync(0xffffffffu, sq, 2);
    sq += __shfl_xor_sync(0xffffffffu, sq, 4);
    sq += __shfl_xor_sync(0xffffffffu, sq, 8);
    return (sqrtf(sq) / (1.0f + sq)) * s;
}

// ---------------- K1: u_hat (fp16 pair-packed, f-order) + raw s0 into S0 -----------
// Lane l owns flats {4l..4l+3, 128+l}: vectorized STG.128/STS.128 stores.
// Quad-buffered part -> __syncthreads every 4 pairs.
#define K1_NBCH 2
#define K1_BCH  (NB / K1_NBCH)    // 256 b
#define K1_NP   (K1_BCH / 2)      // 128 pairs per block

__global__ __launch_bounds__(256, 2) void k1_uhat(const float* __restrict__ u,
                                                  const float* __restrict__ W) {
    __shared__ __align__(16) float2 part[4][8][CO];   // 40 KB

    const int w = threadIdx.x >> 5;
    const int l = threadIdx.x & 31;
    const int r = blockIdx.x * 8 + w;
    const int b0 = blockIdx.y * K1_BCH;
    const int pairbase = b0 >> 1;

    ull  Wp01[8], Wp23[8];
    float Wf4[8];
    {
        float Ws[5][8];
        const int fs[5] = {4 * l, 4 * l + 1, 4 * l + 2, 4 * l + 3, 128 + l};
#pragma unroll
        for (int k = 0; k < 5; k++) {
            int f = fs[k];
            int c = (f % 40) >> 2;
            int o = (f / 40) * 4 + (f & 3);
            const float* Wq = W + ((size_t)r * NC + c) * 128 + o;
#pragma unroll
            for (int i = 0; i < 8; i++) Ws[k][i] = __ldg(Wq + i * 16);
        }
#pragma unroll
        for (int i = 0; i < 8; i++) {
            Wp01[i] = pk2(Ws[0][i], Ws[1][i]);
            Wp23[i] = pk2(Ws[2][i], Ws[3][i]);
            Wf4[i]  = Ws[4][i];
        }
    }

    const float4* u4 = reinterpret_cast<const float4*>(u);

    auto loadU = [&](float4* P, int bp) {
        const int b = b0 + 2 * bp;
        P[0] = __ldg(&u4[((size_t)b * NR + r) * 2]);
        P[1] = __ldg(&u4[((size_t)b * NR + r) * 2 + 1]);
        P[2] = __ldg(&u4[((size_t)(b + 1) * NR + r) * 2]);
        P[3] = __ldg(&u4[((size_t)(b + 1) * NR + r) * 2 + 1]);
    };

    auto computeOne = [&](const float4* P, int bp, int buf) {
        float ue[8] = {P[0].x, P[0].y, P[0].z, P[0].w, P[1].x, P[1].y, P[1].z, P[1].w};
        float uo[8] = {P[2].x, P[2].y, P[2].z, P[2].w, P[3].x, P[3].y, P[3].z, P[3].w};

        ull a01e = 0ULL, a23e = 0ULL, a01o = 0ULL, a23o = 0ULL;
        float a4e = 0.f, a4o = 0.f;
#pragma unroll
        for (int i = 0; i < 8; i++) {
            ull de = pk2(ue[i], ue[i]);
            ull dq = pk2(uo[i], uo[i]);
            fma2(a01e, de, Wp01[i]);
            fma2(a23e, de, Wp23[i]);
            fma2(a01o, dq, Wp01[i]);
            fma2(a23o, dq, Wp23[i]);
            a4e = fmaf(ue[i], Wf4[i], a4e);
            a4o = fmaf(uo[i], Wf4[i], a4o);
        }
        float2 f01e = upk2(a01e), f23e = upk2(a23e);
        float2 f01o = upk2(a01o), f23o = upk2(a23o);

        __half2* outp = g_uhat2 + ((size_t)(pairbase + bp) * NR + r) * CO;
        __half2 h0 = __floats2half2_rn(f01e.x, f01o.x);   // flat 4l
        __half2 h1 = __floats2half2_rn(f01e.y, f01o.y);   // flat 4l+1
        __half2 h2 = __floats2half2_rn(f23e.x, f23o.x);   // flat 4l+2
        __half2 h3 = __floats2half2_rn(f23e.y, f23o.y);   // flat 4l+3
        uint4 pkt;
        pkt.x = *reinterpret_cast<unsigned*>(&h0);
        pkt.y = *reinterpret_cast<unsigned*>(&h1);
        pkt.z = *reinterpret_cast<unsigned*>(&h2);
        pkt.w = *reinterpret_cast<unsigned*>(&h3);
        reinterpret_cast<uint4*>(outp)[l] = pkt;           // STG.128
        outp[128 + l] = __floats2half2_rn(a4e, a4o);       // STG.32

        float4* pr = reinterpret_cast<float4*>(&part[buf][w][0]);
        pr[2 * l]     = make_float4(f01e.x, f01o.x, f01e.y, f01o.y);  // STS.128
        pr[2 * l + 1] = make_float4(f23e.x, f23o.x, f23e.y, f23o.y);  // STS.128
        part[buf][w][128 + l] = make_float2(a4e, a4o);                // STS.64
    };

    auto reduceQuad = [&](int bpEven) {
        __syncthreads();
        const int gp = pairbase + bpEven;
        for (int task = threadIdx.x; task < 4 * CO; task += 256) {
            int d = task / CO, s = task - d * CO;
            float sx = 0.f, sy = 0.f;
#pragma unroll
            for (int ww = 0; ww < 8; ww++) {
                float2 v = part[d][ww][s];
                sx += v.x; sy += v.y;
            }
            redg_v2(&g_S0[(size_t)(gp + d) * CO + s], sx, sy);
        }
        __syncthreads();
    };

    float4 A[4], B[4], C[4], D[4];
    loadU(A, 0); loadU(B, 1);

    for (int t = 0; t < K1_NP; t += 4) {
        loadU(C, t + 2); loadU(D, t + 3);
        computeOne(A, t, 0);
        computeOne(B, t + 1, 1);
        if (t + 4 < K1_NP) { loadU(A, t + 4); loadU(B, t + 5); }
        computeOne(C, t + 2, 2);
        computeOne(D, t + 3, 3);
        reduceQuad(t);
    }
}

// ---------------- pass: routing iteration; V recomputed locally from S-buffers ------
#define RPB     128
#define RCHUNKS (NR / RPB)   // 9

union Q { uint4 v; __half2 h[4]; };

// Two-pass squash accumulation directly into fp16 V — tiny register footprint.
// squash(scale*s): q = scale^2*|s|^2, factor = sqrt(q)/(1+q)*scale applied to raw s.
__device__ __forceinline__ void add_squash_h(const float2* __restrict__ S,
                                             int b2, int c, float scale,
                                             __half2* __restrict__ Vh) {
    const float4* p4 = reinterpret_cast<const float4*>(S + (size_t)b2 * CO);
    float ssx = 0.f, ssy = 0.f;
#pragma unroll
    for (int oc = 0; oc < 4; oc++)
#pragma unroll
        for (int p = 0; p < 2; p++) {
            float4 t = __ldg(p4 + oc * 20 + c * 2 + p);
            ssx = fmaf(t.x, t.x, fmaf(t.z, t.z, ssx));
            ssy = fmaf(t.y, t.y, fmaf(t.w, t.w, ssy));
        }
    float qx = scale * scale * ssx, qy = scale * scale * ssy;
    float fx = sqrtf(qx) / (1.0f + qx) * scale;
    float fy = sqrtf(qy) / (1.0f + qy) * scale;
#pragma unroll
    for (int oc = 0; oc < 4; oc++)
#pragma unroll
        for (int p = 0; p < 2; p++) {
            float4 t = __ldg(p4 + oc * 20 + c * 2 + p);   // L1-hot reload
            int o = oc * 4 + 2 * p;
            Vh[o]     = __hadd2(Vh[o],     __floats2half2_rn(fx * t.x, fy * t.y));
            Vh[o + 1] = __hadd2(Vh[o + 1], __floats2half2_rn(fx * t.z, fy * t.w));
        }
}

__global__ __launch_bounds__(256, 4) void k_pass(float* __restrict__ outp,
                                                 int final_iter) {
    __shared__ float2 part[8][CO];
    __shared__ int lastFlag;

    const int w = threadIdx.x >> 5;
    const int l = threadIdx.x & 31;
    const int b2 = blockIdx.x;
    const int rbase = blockIdx.y * RPB;
    const int g = l >> 4;
    const int c = l & 15;
    const bool act = (c < NC);

    const __half2 hz = __floats2half2_rn(0.f, 0.f);

    // ---- V prologue: Vh = squash(0.1*S0) [+ squash(S1) on final iter], fp16 -------
    __half2 Vh[16];
#pragma unroll
    for (int o = 0; o < 16; o++) Vh[o] = hz;
    if (act) {
        add_squash_h(g_S0, b2, c, 0.1f, Vh);
        if (final_iter) add_squash_h(g_S1, b2, c, 1.0f, Vh);
    }

    __half2 acch[16];
#pragma unroll
    for (int o = 0; o < 16; o++) acch[o] = hz;

    const __half2* base = g_uhat2 + (size_t)b2 * NR * CO + c * 4;
#define PASS_ROW(j) (base + (size_t)(rbase + 2 * (w * 8 + (j)) + g) * CO)

    auto loadq = [&](Q* q, int j) {
        const __half2* rp = PASS_ROW(j);
        q[0].v = __ldg(reinterpret_cast<const uint4*>(rp));
        q[1].v = __ldg(reinterpret_cast<const uint4*>(rp + 40));
        q[2].v = __ldg(reinterpret_cast<const uint4*>(rp + 80));
        q[3].v = __ldg(reinterpret_cast<const uint4*>(rp + 120));
    };

    auto body = [&](Q* q) {
        // fp16 dot: 16 HFMA2 in two chains, no unpack
        __half2 dh0 = hz, dh1 = hz;
        if (act) {
#pragma unroll
            for (int qq = 0; qq < 4; qq++)
#pragma unroll
                for (int m = 0; m < 4; m++) {
                    int o = qq * 4 + m;
                    if (m & 1) dh1 = __hfma2(q[qq].h[m], Vh[o], dh1);
                    else       dh0 = __hfma2(q[qq].h[m], Vh[o], dh0);
                }
        }
        float2 d = __half22float2(__hadd2(dh0, dh1));
        float e0 = act ? __expf(d.x) : 0.0f;        // |logit| small: no max-shift
        float e1 = act ? __expf(d.y) : 0.0f;
        float s0 = e0, s1 = e1;
#pragma unroll
        for (int dl = 1; dl <= 8; dl <<= 1) {
            s0 += __shfl_xor_sync(0xffffffffu, s0, dl);
            s1 += __shfl_xor_sync(0xffffffffu, s1, dl);
        }
        // fp16 accumulate on raw half2: 16 HFMA2, zero unpack/pack
        if (act) {
            __half2 ph = __floats2half2_rn(e0 * __frcp_rn(s0), e1 * __frcp_rn(s1));
#pragma unroll
            for (int qq = 0; qq < 4; qq++)
#pragma unroll
                for (int m = 0; m < 4; m++)
                    acch[qq * 4 + m] = __hfma2(q[qq].h[m], ph, acch[qq * 4 + m]);
        }
    };

    // single q buffer: fits 4 CTAs/SM; cross-warp parallelism hides the chain
    Q qa[4];
#pragma unroll
    for (int j = 0; j < 8; j++) {
        if (act) loadq(qa, j);
        body(qa);
    }

    // flush fp16 -> f32, combine the two 16-lane r-groups, stage into smem (f-order)
#pragma unroll
    for (int o = 0; o < 16; o++) {
        float2 a = __half22float2(acch[o]);
        a.x += __shfl_xor_sync(0xffffffffu, a.x, 16);
        a.y += __shfl_xor_sync(0xffffffffu, a.y, 16);
        if (g == 0 && act) part[w][(o >> 2) * 40 + c * 4 + (o & 3)] = a;
    }
    __syncthreads();

    float2* Sdst = final_iter ? g_S2 : g_S1;
    if (threadIdx.x < CO) {
        float sx = 0.f, sy = 0.f;
#pragma unroll
        for (int ww = 0; ww < 8; ww++) {
            float2 v = part[ww][threadIdx.x];
            sx += v.x; sy += v.y;
        }
        redg_v2(&Sdst[b2 * CO + threadIdx.x], sx, sy);
    }

    if (!final_iter) return;   // pass 1 has no tail

    // ---- pass-2 tail: last of the 9 blocks for this b2 squashes & resets ----------
    __threadfence();
    __syncthreads();
    if (threadIdx.x == 0)
        lastFlag = (atomicAdd(&g_cnt[b2], 1) == RCHUNKS - 1);
    __syncthreads();

    if (lastFlag) {
        __threadfence();
        const int t = threadIdx.x;
        if (t < CO) {                       // 16-lane groups = classes
            int f = ((t & 15) >> 2) * 40 + ((t >> 4) << 2) + (t & 3);
            float2 sv = g_S2[b2 * CO + f];
            float vx = squash_val(sv.x);
            float vy = squash_val(sv.y);
            outp[(2 * b2) * CO + t]     = vx;
            outp[(2 * b2 + 1) * CO + t] = vy;
            g_S0[b2 * CO + f] = make_float2(0.f, 0.f);   // replay invariants
            g_S1[b2 * CO + f] = make_float2(0.f, 0.f);
            g_S2[b2 * CO + f] = make_float2(0.f, 0.f);
        }
        if (threadIdx.x == 0) g_cnt[b2] = 0;
    }
}

// ---------------- launch -------------------------------------------------------------
extern "C" void kernel_launch(void* const* d_in, const int* in_sizes, int n_in,
                              void* d_out, int out_size) {
    const float* u = (const float*)d_in[0];   // [512,1152,8]
    const float* W = (const float*)d_in[1];   // [1,1152,10,8,16]
    float* outp = (float*)d_out;              // [512,10,16]

    k1_uhat<<<dim3(NR / 8, K1_NBCH), 256>>>(u, W);     // u_hat + raw s0 -> S0
    k_pass<<<dim3(NB2, RCHUNKS), 256>>>(outp, 0);      // iter 1 -> S1
    k_pass<<<dim3(NB2, RCHUNKS), 256>>>(outp, 1);      // iter 2 -> S2 -> out, resets
}